// round 1
// baseline (speedup 1.0000x reference)
#include <cuda_runtime.h>
#include <math.h>

#define NN 50000
#define NE 600000
#define OBSD 256
#define EHID 512
#define HD 128
#define NH 8

// ---------------- scratch (device globals; no allocation allowed) ----------------
__device__ float g_h1[(size_t)NN * EHID];
__device__ float g_z1[(size_t)NN * HD];
__device__ float g_z2[(size_t)NN * HD];
__device__ float g_z3[(size_t)NN * HD];
__device__ float g_feat[(size_t)NN * HD];
__device__ float g_el[(size_t)NN * NH];
__device__ float g_er[(size_t)NN * NH];
__device__ int   g_deg[NN];
__device__ int   g_off[NN + 1];
__device__ int   g_pos[NN];
__device__ int   g_csr_src[NE];

// ---------------- CSR build ----------------
__global__ void k_zero_deg() {
    int i = blockIdx.x * blockDim.x + threadIdx.x;
    if (i < NN) g_deg[i] = 0;
}

__global__ void k_hist(const int* __restrict__ dst) {
    int i = blockIdx.x * blockDim.x + threadIdx.x;
    if (i < NE) atomicAdd(&g_deg[dst[i]], 1);
}

// single-block exclusive scan over g_deg -> g_off, g_pos
__global__ void k_scan() {
    __shared__ int warpsums[32];
    __shared__ int s_run;
    int tid = threadIdx.x, lane = tid & 31, wid = tid >> 5;
    if (tid == 0) s_run = 0;
    __syncthreads();
    for (int base = 0; base < NN; base += 1024) {
        int i = base + tid;
        int v = (i < NN) ? g_deg[i] : 0;
        int x = v;
        #pragma unroll
        for (int s = 1; s < 32; s <<= 1) {
            int t = __shfl_up_sync(0xffffffffu, x, s);
            if (lane >= s) x += t;
        }
        if (lane == 31) warpsums[wid] = x;
        __syncthreads();
        if (wid == 0) {
            int w = warpsums[lane];
            #pragma unroll
            for (int s = 1; s < 32; s <<= 1) {
                int t = __shfl_up_sync(0xffffffffu, w, s);
                if (lane >= s) w += t;
            }
            warpsums[lane] = w;
        }
        __syncthreads();
        int chunk_total = warpsums[31];
        int prefix = s_run + ((wid > 0) ? warpsums[wid - 1] : 0) + x - v; // exclusive
        if (i < NN) { g_off[i] = prefix; g_pos[i] = prefix; }
        __syncthreads();
        if (tid == 0) s_run += chunk_total;
        __syncthreads();
    }
    if (threadIdx.x == 0) g_off[NN] = s_run;
}

__global__ void k_scatter(const int* __restrict__ src, const int* __restrict__ dst) {
    int i = blockIdx.x * blockDim.x + threadIdx.x;
    if (i < NE) {
        int p = atomicAdd(&g_pos[dst[i]], 1);
        g_csr_src[p] = src[i];
    }
}

// ---------------- fp32 register-tiled GEMM: C = relu?(A@B + bias) ----------------
// A: [M,K] row-major, B: [K,N] row-major. BM=BN=128, BK=8, 256 threads, 8x8 microtile.
// Requires N % 128 == 0, K % 8 == 0 (true for all calls). M guarded.
__global__ __launch_bounds__(256) void gemm_kernel(
    const float* __restrict__ A, const float* __restrict__ B,
    const float* __restrict__ bias, float* __restrict__ C,
    float* __restrict__ C2, int c2_stride, int c2_base,
    int M, int N, int K, int doRelu)
{
    __shared__ float As[8][132];
    __shared__ float Bs[8][128];
    int tid = threadIdx.x;
    int row0 = blockIdx.y * 128, col0 = blockIdx.x * 128;
    int tx = tid & 15, ty = tid >> 4;
    int arow = tid >> 1, ac4 = (tid & 1) * 4;
    int brow = tid >> 5, bcol = (tid & 31) * 4;

    float acc[8][8];
    #pragma unroll
    for (int i = 0; i < 8; i++)
        #pragma unroll
        for (int j = 0; j < 8; j++) acc[i][j] = 0.f;

    for (int k0 = 0; k0 < K; k0 += 8) {
        float4 av = make_float4(0.f, 0.f, 0.f, 0.f);
        int gr = row0 + arow;
        if (gr < M) av = *(const float4*)(A + (size_t)gr * K + k0 + ac4);
        As[ac4 + 0][arow] = av.x;
        As[ac4 + 1][arow] = av.y;
        As[ac4 + 2][arow] = av.z;
        As[ac4 + 3][arow] = av.w;
        float4 bv = *(const float4*)(B + (size_t)(k0 + brow) * N + col0 + bcol);
        *(float4*)&Bs[brow][bcol] = bv;
        __syncthreads();
        #pragma unroll
        for (int k = 0; k < 8; k++) {
            float a[8], b[8];
            *(float4*)(a)     = *(const float4*)&As[k][ty * 8];
            *(float4*)(a + 4) = *(const float4*)&As[k][ty * 8 + 4];
            *(float4*)(b)     = *(const float4*)&Bs[k][tx * 8];
            *(float4*)(b + 4) = *(const float4*)&Bs[k][tx * 8 + 4];
            #pragma unroll
            for (int i = 0; i < 8; i++)
                #pragma unroll
                for (int j = 0; j < 8; j++)
                    acc[i][j] = fmaf(a[i], b[j], acc[i][j]);
        }
        __syncthreads();
    }

    #pragma unroll
    for (int i = 0; i < 8; i++) {
        int gr = row0 + ty * 8 + i;
        if (gr >= M) continue;
        #pragma unroll
        for (int j = 0; j < 8; j += 4) {
            int gc = col0 + tx * 8 + j;
            float4 v;
            v.x = acc[i][j + 0]; v.y = acc[i][j + 1];
            v.z = acc[i][j + 2]; v.w = acc[i][j + 3];
            if (bias) {
                v.x += bias[gc + 0]; v.y += bias[gc + 1];
                v.z += bias[gc + 2]; v.w += bias[gc + 3];
            }
            if (doRelu) {
                v.x = fmaxf(v.x, 0.f); v.y = fmaxf(v.y, 0.f);
                v.z = fmaxf(v.z, 0.f); v.w = fmaxf(v.w, 0.f);
            }
            *(float4*)(C + (size_t)gr * N + gc) = v;
            if (C2) *(float4*)(C2 + (size_t)gr * c2_stride + c2_base + gc) = v;
        }
    }
}

// ---------------- per-(node,head) attention logits el/er ----------------
__global__ void k_elr(const float* __restrict__ feat,
                      const float* __restrict__ al, const float* __restrict__ ar,
                      float* __restrict__ el, float* __restrict__ er)
{
    int idx = blockIdx.x * blockDim.x + threadIdx.x;
    if (idx >= NN * NH) return;
    int n = idx >> 3, h = idx & 7;
    const float* f = feat + (size_t)n * HD + h * 16;
    const float4* a4 = (const float4*)(al + h * 16);
    const float4* r4 = (const float4*)(ar + h * 16);
    float sl = 0.f, sr = 0.f;
    #pragma unroll
    for (int d = 0; d < 4; d++) {
        float4 fv = *(const float4*)(f + d * 4);
        float4 av = __ldg(a4 + d);
        float4 rv = __ldg(r4 + d);
        sl += fv.x * av.x + fv.y * av.y + fv.z * av.z + fv.w * av.w;
        sr += fv.x * rv.x + fv.y * rv.y + fv.z * rv.z + fv.w * rv.w;
    }
    el[idx] = sl;
    er[idx] = sr;
}

// ---------------- warp-per-node GAT softmax + aggregation ----------------
__global__ __launch_bounds__(128) void gat_edge(
    const float* __restrict__ el, const float* __restrict__ er,
    const float* __restrict__ feat,
    float* __restrict__ zout, float* __restrict__ out, int out_base)
{
    int n = blockIdx.x * 4 + (threadIdx.x >> 5);
    if (n >= NN) return;
    int lane = threadIdx.x & 31;
    int off = g_off[n];
    int deg = g_off[n + 1] - off;

    const float NEG_INF = -__int_as_float(0x7f800000); // -inf

    // phase A/B layout: lane covers head h = lane&7, edge-sub = lane>>3 (4 edges/chunk)
    int h = lane & 7, esub = lane >> 3;
    float er_h = er[(size_t)n * NH + h];

    float m = NEG_INF;
    for (int e0 = 0; e0 < deg; e0 += 4) {
        int e = e0 + esub;
        float x = NEG_INF;
        if (e < deg) {
            int s = g_csr_src[off + e];
            float t = el[(size_t)s * NH + h] + er_h;
            x = (t > 0.f) ? t : 0.2f * t;
        }
        m = fmaxf(m, x);
    }
    m = fmaxf(m, __shfl_xor_sync(0xffffffffu, m, 8));
    m = fmaxf(m, __shfl_xor_sync(0xffffffffu, m, 16));
    if (!isfinite(m)) m = 0.f; // empty segment

    float zs = 0.f;
    for (int e0 = 0; e0 < deg; e0 += 4) {
        int e = e0 + esub;
        if (e < deg) {
            int s = g_csr_src[off + e];
            float t = el[(size_t)s * NH + h] + er_h;
            t = (t > 0.f) ? t : 0.2f * t;
            zs += __expf(t - m);
        }
    }
    zs += __shfl_xor_sync(0xffffffffu, zs, 8);
    zs += __shfl_xor_sync(0xffffffffu, zs, 16);
    float zinv = 1.f / (zs + 1e-9f);

    // phase C layout: lane owns features [lane*4, lane*4+4), head hc = lane>>2
    int hc = lane >> 2;
    float m_c  = __shfl_sync(0xffffffffu, m, hc);
    float zi_c = __shfl_sync(0xffffffffu, zinv, hc);
    float er_c = __shfl_sync(0xffffffffu, er_h, hc);

    float4 acc = make_float4(0.f, 0.f, 0.f, 0.f);
    for (int e = 0; e < deg; e++) {
        int s = g_csr_src[off + e];
        float t = el[(size_t)s * NH + hc] + er_c;
        t = (t > 0.f) ? t : 0.2f * t;
        float w = __expf(t - m_c) * zi_c;
        float4 f = *(const float4*)(feat + (size_t)s * HD + lane * 4);
        acc.x = fmaf(f.x, w, acc.x);
        acc.y = fmaf(f.y, w, acc.y);
        acc.z = fmaf(f.z, w, acc.z);
        acc.w = fmaf(f.w, w, acc.w);
    }
    acc.x = fmaxf(acc.x, 0.f); acc.y = fmaxf(acc.y, 0.f);
    acc.z = fmaxf(acc.z, 0.f); acc.w = fmaxf(acc.w, 0.f);

    *(float4*)(zout + (size_t)n * HD + lane * 4) = acc;
    *(float4*)(out + (size_t)n * 384 + out_base + lane * 4) = acc;
}

// ---------------- launcher ----------------
extern "C" void kernel_launch(void* const* d_in, const int* in_sizes, int n_in,
                              void* d_out, int out_size)
{
    const float* obs = (const float*)d_in[0];
    const int*   src = (const int*)d_in[1];
    const int*   dst = (const int*)d_in[2];
    const float* W1  = (const float*)d_in[3];
    const float* b1  = (const float*)d_in[4];
    const float* W2  = (const float*)d_in[5];
    const float* b2  = (const float*)d_in[6];
    const float* Wg1 = (const float*)d_in[7];
    const float* al1 = (const float*)d_in[8];
    const float* ar1 = (const float*)d_in[9];
    const float* Wg2 = (const float*)d_in[10];
    const float* al2 = (const float*)d_in[11];
    const float* ar2 = (const float*)d_in[12];
    float* out = (float*)d_out;

    float *h1, *z1, *z2, *z3, *feat, *el, *er;
    cudaGetSymbolAddress((void**)&h1,   g_h1);
    cudaGetSymbolAddress((void**)&z1,   g_z1);
    cudaGetSymbolAddress((void**)&z2,   g_z2);
    cudaGetSymbolAddress((void**)&z3,   g_z3);
    cudaGetSymbolAddress((void**)&feat, g_feat);
    cudaGetSymbolAddress((void**)&el,   g_el);
    cudaGetSymbolAddress((void**)&er,   g_er);

    // CSR build (recomputed every call; deterministic work)
    k_zero_deg<<<(NN + 255) / 256, 256>>>();
    k_hist<<<(NE + 255) / 256, 256>>>(dst);
    k_scan<<<1, 1024>>>();
    k_scatter<<<(NE + 255) / 256, 256>>>(src, dst);

    dim3 thr(256);
    // MLP: h1 = relu(obs@W1+b1) ; z1 = relu(h1@W2+b2) (also written to out[:,0:128])
    gemm_kernel<<<dim3(EHID / 128, (NN + 127) / 128), thr>>>(
        obs, W1, b1, h1, nullptr, 0, 0, NN, EHID, OBSD, 1);
    gemm_kernel<<<dim3(HD / 128, (NN + 127) / 128), thr>>>(
        h1, W2, b2, z1, out, 384, 0, NN, HD, EHID, 1);

    // GAT layer 1
    gemm_kernel<<<dim3(HD / 128, (NN + 127) / 128), thr>>>(
        z1, Wg1, nullptr, feat, nullptr, 0, 0, NN, HD, HD, 0);
    k_elr<<<(NN * NH + 255) / 256, 256>>>(feat, al1, ar1, el, er);
    gat_edge<<<(NN + 3) / 4, 128>>>(el, er, feat, z2, out, 128);

    // GAT layer 2
    gemm_kernel<<<dim3(HD / 128, (NN + 127) / 128), thr>>>(
        z2, Wg2, nullptr, feat, nullptr, 0, 0, NN, HD, HD, 0);
    k_elr<<<(NN * NH + 255) / 256, 256>>>(feat, al2, ar2, el, er);
    gat_edge<<<(NN + 3) / 4, 128>>>(el, er, feat, z3, out, 256);
}

// round 3
// speedup vs baseline: 2.0432x; 2.0432x over previous
#include <cuda_runtime.h>
#include <cuda_bf16.h>
#include <math.h>
#include <stdint.h>

#define NN 50000
#define NE 600000
#define OBSD 256
#define EHID 512
#define HD 128
#define NH 8

// ---------------- scratch (device globals; no allocation allowed) ----------------
__device__ __align__(16) float g_h1[(size_t)NN * EHID];
__device__ __align__(16) float g_z1[(size_t)NN * HD];
__device__ __align__(16) float g_z2[(size_t)NN * HD];
__device__ __align__(16) float g_z3[(size_t)NN * HD];
__device__ __align__(16) float g_feat[(size_t)NN * HD];
__device__ __align__(16) float g_el[(size_t)NN * NH];
__device__ __align__(16) float g_er[(size_t)NN * NH];
__device__ int   g_deg[NN];
__device__ int   g_off[NN + 1];
__device__ int   g_pos[NN];
__device__ int   g_csr_src[NE];

// transposed + bf16-split weights: [N,K] K-major, hi and lo planes
#define W1T_OFF  0
#define W2T_OFF  (512*256)
#define WG1T_OFF (W2T_OFF + 128*512)
#define WG2T_OFF (WG1T_OFF + 128*128)
#define WT_TOTAL (WG2T_OFF + 128*128)
__device__ __align__(16) __nv_bfloat16 g_wt_hi[WT_TOTAL];
__device__ __align__(16) __nv_bfloat16 g_wt_lo[WT_TOTAL];

// ---------------- PTX helpers (baseline sm_80+ features only) ----------------
__device__ __forceinline__ uint32_t smem_u32(const void* p) {
    uint32_t a;
    asm("{ .reg .u64 t; cvta.to.shared.u64 t, %1; cvt.u32.u64 %0, t; }" : "=r"(a) : "l"(p));
    return a;
}

__device__ __forceinline__ void ldsm_x4(uint32_t& r0, uint32_t& r1, uint32_t& r2, uint32_t& r3,
                                        uint32_t addr) {
    asm volatile("ldmatrix.sync.aligned.m8n8.x4.shared.b16 {%0,%1,%2,%3}, [%4];"
                 : "=r"(r0), "=r"(r1), "=r"(r2), "=r"(r3) : "r"(addr));
}

__device__ __forceinline__ void mma_bf16(float* c,
                                         uint32_t a0, uint32_t a1, uint32_t a2, uint32_t a3,
                                         uint32_t b0, uint32_t b1) {
    asm volatile("mma.sync.aligned.m16n8k16.row.col.f32.bf16.bf16.f32 "
                 "{%0,%1,%2,%3}, {%4,%5,%6,%7}, {%8,%9}, {%0,%1,%2,%3};"
                 : "+f"(c[0]), "+f"(c[1]), "+f"(c[2]), "+f"(c[3])
                 : "r"(a0), "r"(a1), "r"(a2), "r"(a3), "r"(b0), "r"(b1));
}

__device__ __forceinline__ uint32_t sw128(uint32_t byte) {
    return byte ^ ((byte >> 3) & 0x70u);
}

__device__ __forceinline__ uint32_t pack_bf2(__nv_bfloat16 a, __nv_bfloat16 b) {
    __nv_bfloat162 t = __halves2bfloat162(a, b);
    return *reinterpret_cast<uint32_t*>(&t);
}

// ---------------- CSR build ----------------
__global__ void k_zero_deg() {
    int i = blockIdx.x * blockDim.x + threadIdx.x;
    if (i < NN) g_deg[i] = 0;
}

__global__ void k_hist(const int* __restrict__ dst) {
    int i = blockIdx.x * blockDim.x + threadIdx.x;
    if (i < NE) atomicAdd(&g_deg[dst[i]], 1);
}

__global__ void k_scan() {
    __shared__ int warpsums[32];
    __shared__ int s_run;
    int tid = threadIdx.x, lane = tid & 31, wid = tid >> 5;
    if (tid == 0) s_run = 0;
    __syncthreads();
    for (int base = 0; base < NN; base += 1024) {
        int i = base + tid;
        int v = (i < NN) ? g_deg[i] : 0;
        int x = v;
        #pragma unroll
        for (int s = 1; s < 32; s <<= 1) {
            int t = __shfl_up_sync(0xffffffffu, x, s);
            if (lane >= s) x += t;
        }
        if (lane == 31) warpsums[wid] = x;
        __syncthreads();
        if (wid == 0) {
            int w = warpsums[lane];
            #pragma unroll
            for (int s = 1; s < 32; s <<= 1) {
                int t = __shfl_up_sync(0xffffffffu, w, s);
                if (lane >= s) w += t;
            }
            warpsums[lane] = w;
        }
        __syncthreads();
        int chunk_total = warpsums[31];
        int prefix = s_run + ((wid > 0) ? warpsums[wid - 1] : 0) + x - v;
        if (i < NN) { g_off[i] = prefix; g_pos[i] = prefix; }
        __syncthreads();
        if (tid == 0) s_run += chunk_total;
        __syncthreads();
    }
    if (threadIdx.x == 0) g_off[NN] = s_run;
}

__global__ void k_scatter(const int* __restrict__ src, const int* __restrict__ dst) {
    int i = blockIdx.x * blockDim.x + threadIdx.x;
    if (i < NE) {
        int p = atomicAdd(&g_pos[dst[i]], 1);
        g_csr_src[p] = src[i];
    }
}

// ---------------- weight transpose + bf16 split: Wt[n,k] = W[k,n] ----------------
__global__ void k_split(const float* __restrict__ W, int K, int N,
                        __nv_bfloat16* __restrict__ hi, __nv_bfloat16* __restrict__ lo) {
    int idx = blockIdx.x * blockDim.x + threadIdx.x;
    if (idx >= N * K) return;
    int n = idx / K, k = idx - n * K;
    float x = W[(size_t)k * N + n];
    __nv_bfloat16 h = __float2bfloat16(x);
    hi[idx] = h;
    lo[idx] = __float2bfloat16(x - __bfloat162float(h));
}

// ---------------- bf16x3 mma.sync GEMM: C = relu?(A@B + bias) ----------------
// A: [M,K] fp32 row-major.  Bhi/Blo: [N,K] bf16 K-major.
// CTA tile 128x128, K-chunk 64. 256 threads = 8 warps, warp tile 64x32
// (warp_m = wid&1 -> 2x64 rows, warp_n = wid>>1 -> 4x32 cols).
// smem planes (128 rows x 128B, SW128 swizzle): Ahi, Alo, Bhi, Blo.
#define SMA_HI 0
#define SMA_LO 16384
#define SMB_HI 32768
#define SMB_LO 49152
#define SM_TOTAL 65536

__global__ __launch_bounds__(256) void gemm_mma(
    const float* __restrict__ A,
    const __nv_bfloat16* __restrict__ Bhi, const __nv_bfloat16* __restrict__ Blo,
    const float* __restrict__ bias,
    float* __restrict__ C, float* __restrict__ C2, int c2_stride, int c2_base,
    int M, int N, int K, int doRelu)
{
    extern __shared__ char sm[];
    uint32_t sb = smem_u32(sm);
    int tid = threadIdx.x, wid = tid >> 5, lane = tid & 31;
    int row0 = blockIdx.y * 128, col0 = blockIdx.x * 128;
    int wm = wid & 1, wn = wid >> 1;

    float acc[4][4][4];
    #pragma unroll
    for (int i = 0; i < 4; i++)
        #pragma unroll
        for (int j = 0; j < 4; j++)
            #pragma unroll
            for (int r = 0; r < 4; r++) acc[i][j][r] = 0.f;

    // ldmatrix lane address components
    // A frag (16x16): lanes 0-7 m0(rows0-7,k0-7), 8-15 m1(rows8-15,k0-7),
    //                 16-23 m2(rows0-7,k8-15), 24-31 m3(rows8-15,k8-15)
    int a_r  = lane & 15;                 // row within 16-row frag
    int a_kb = (lane >> 4) * 16;          // byte offset of k-half (8 bf16 = 16B)
    // B frag pair (16 n x 16 k): m0(n0-7,k0-7) m1(n0-7,k8-15) m2(n8-15,k0-7) m3(n8-15,k8-15)
    int b_n  = (lane & 7) + ((lane >> 4) & 1) * 8;
    int b_kb = ((lane >> 3) & 1) * 16;

    for (int c = 0; c < K / 64; c++) {
        int k0 = c * 64;
        // ---- load + split A tile: 128 rows x 64 cols fp32 -> hi/lo bf16 ----
        #pragma unroll
        for (int i = 0; i < 8; i++) {
            int idx = tid + i * 256;
            int r = idx >> 4, c4 = (idx & 15) << 2;
            float4 v = make_float4(0.f, 0.f, 0.f, 0.f);
            int gr = row0 + r;
            if (gr < M) v = *(const float4*)(A + (size_t)gr * K + k0 + c4);
            __nv_bfloat16 hx = __float2bfloat16(v.x), hy = __float2bfloat16(v.y);
            __nv_bfloat16 hz = __float2bfloat16(v.z), hw = __float2bfloat16(v.w);
            __nv_bfloat16 lx = __float2bfloat16(v.x - __bfloat162float(hx));
            __nv_bfloat16 ly = __float2bfloat16(v.y - __bfloat162float(hy));
            __nv_bfloat16 lz = __float2bfloat16(v.z - __bfloat162float(hz));
            __nv_bfloat16 lw = __float2bfloat16(v.w - __bfloat162float(hw));
            uint32_t sw = sw128((uint32_t)(r * 128 + c4 * 2));
            *(uint32_t*)(sm + SMA_HI + sw)     = pack_bf2(hx, hy);
            *(uint32_t*)(sm + SMA_HI + sw + 4) = pack_bf2(hz, hw);
            *(uint32_t*)(sm + SMA_LO + sw)     = pack_bf2(lx, ly);
            *(uint32_t*)(sm + SMA_LO + sw + 4) = pack_bf2(lz, lw);
        }
        // ---- load B tiles: 128 n-rows x 64 k bf16 (hi and lo) ----
        #pragma unroll
        for (int i = 0; i < 4; i++) {
            int idx = tid + i * 256;
            int r = idx >> 3, c8 = (idx & 7) << 3;
            size_t goff = (size_t)(col0 + r) * K + k0 + c8;
            uint4 vh = *(const uint4*)(Bhi + goff);
            uint4 vl = *(const uint4*)(Blo + goff);
            uint32_t sw = sw128((uint32_t)(r * 128 + c8 * 2));
            *(uint4*)(sm + SMB_HI + sw) = vh;
            *(uint4*)(sm + SMB_LO + sw) = vl;
        }
        __syncthreads();

        // ---- 3 precision planes: (Ahi,Bhi), (Ahi,Blo), (Alo,Bhi) ----
        #pragma unroll 1
        for (int pl = 0; pl < 3; pl++) {
            uint32_t abase = sb + (pl == 2 ? SMA_LO : SMA_HI);
            uint32_t bbase = sb + (pl == 1 ? SMB_LO : SMB_HI);
            #pragma unroll
            for (int k16 = 0; k16 < 4; k16++) {
                int kb = k16 * 32;  // 16 bf16 = 32 bytes
                uint32_t a[4][4], b[4][2];
                #pragma unroll
                for (int mf = 0; mf < 4; mf++) {
                    uint32_t byte = (uint32_t)((wm * 64 + mf * 16 + a_r) * 128 + kb + a_kb);
                    ldsm_x4(a[mf][0], a[mf][1], a[mf][2], a[mf][3], abase + sw128(byte));
                }
                #pragma unroll
                for (int nfp = 0; nfp < 2; nfp++) {
                    uint32_t byte = (uint32_t)((wn * 32 + nfp * 16 + b_n) * 128 + kb + b_kb);
                    uint32_t r0, r1, r2, r3;
                    ldsm_x4(r0, r1, r2, r3, bbase + sw128(byte));
                    b[nfp * 2][0] = r0; b[nfp * 2][1] = r1;
                    b[nfp * 2 + 1][0] = r2; b[nfp * 2 + 1][1] = r3;
                }
                #pragma unroll
                for (int mf = 0; mf < 4; mf++)
                    #pragma unroll
                    for (int nf = 0; nf < 4; nf++)
                        mma_bf16(acc[mf][nf], a[mf][0], a[mf][1], a[mf][2], a[mf][3],
                                 b[nf][0], b[nf][1]);
            }
        }
        __syncthreads();
    }

    // ---- epilogue ----
    // thread t holds: c0,c1 -> (row = t/4, col = (t%4)*2 + {0,1}); c2,c3 -> row+8
    int er_r = lane >> 2, er_c = (lane & 3) * 2;
    #pragma unroll
    for (int nf = 0; nf < 4; nf++) {
        int gc = col0 + wn * 32 + nf * 8 + er_c;
        float bx = 0.f, by = 0.f;
        if (bias) { bx = __ldg(bias + gc); by = __ldg(bias + gc + 1); }
        #pragma unroll
        for (int mf = 0; mf < 4; mf++) {
            int r_lo = row0 + wm * 64 + mf * 16 + er_r;
            float2 v0, v1;
            v0.x = acc[mf][nf][0] + bx; v0.y = acc[mf][nf][1] + by;
            v1.x = acc[mf][nf][2] + bx; v1.y = acc[mf][nf][3] + by;
            if (doRelu) {
                v0.x = fmaxf(v0.x, 0.f); v0.y = fmaxf(v0.y, 0.f);
                v1.x = fmaxf(v1.x, 0.f); v1.y = fmaxf(v1.y, 0.f);
            }
            if (r_lo < M) {
                *(float2*)(C + (size_t)r_lo * N + gc) = v0;
                if (C2) *(float2*)(C2 + (size_t)r_lo * c2_stride + c2_base + gc) = v0;
            }
            if (r_lo + 8 < M) {
                *(float2*)(C + (size_t)(r_lo + 8) * N + gc) = v1;
                if (C2) *(float2*)(C2 + (size_t)(r_lo + 8) * c2_stride + c2_base + gc) = v1;
            }
        }
    }
}

// ---------------- per-(node,head) attention logits el/er ----------------
__global__ void k_elr(const float* __restrict__ feat,
                      const float* __restrict__ al, const float* __restrict__ ar,
                      float* __restrict__ el, float* __restrict__ er)
{
    int idx = blockIdx.x * blockDim.x + threadIdx.x;
    if (idx >= NN * NH) return;
    int n = idx >> 3, h = idx & 7;
    const float* f = feat + (size_t)n * HD + h * 16;
    const float4* a4 = (const float4*)(al + h * 16);
    const float4* r4 = (const float4*)(ar + h * 16);
    float sl = 0.f, sr = 0.f;
    #pragma unroll
    for (int d = 0; d < 4; d++) {
        float4 fv = *(const float4*)(f + d * 4);
        float4 av = __ldg(a4 + d);
        float4 rv = __ldg(r4 + d);
        sl += fv.x * av.x + fv.y * av.y + fv.z * av.z + fv.w * av.w;
        sr += fv.x * rv.x + fv.y * rv.y + fv.z * rv.z + fv.w * rv.w;
    }
    el[idx] = sl;
    er[idx] = sr;
}

// ---------------- warp-per-node GAT softmax + aggregation ----------------
__global__ __launch_bounds__(128) void gat_edge(
    const float* __restrict__ el, const float* __restrict__ er,
    const float* __restrict__ feat,
    float* __restrict__ zout, float* __restrict__ out, int out_base)
{
    int n = blockIdx.x * 4 + (threadIdx.x >> 5);
    if (n >= NN) return;
    int lane = threadIdx.x & 31;
    int off = g_off[n];
    int deg = g_off[n + 1] - off;

    const float NEG_INF = -__int_as_float(0x7f800000);

    int h = lane & 7, esub = lane >> 3;
    float er_h = er[(size_t)n * NH + h];

    float m = NEG_INF;
    for (int e0 = 0; e0 < deg; e0 += 4) {
        int e = e0 + esub;
        float x = NEG_INF;
        if (e < deg) {
            int s = g_csr_src[off + e];
            float t = el[(size_t)s * NH + h] + er_h;
            x = (t > 0.f) ? t : 0.2f * t;
        }
        m = fmaxf(m, x);
    }
    m = fmaxf(m, __shfl_xor_sync(0xffffffffu, m, 8));
    m = fmaxf(m, __shfl_xor_sync(0xffffffffu, m, 16));
    if (!isfinite(m)) m = 0.f;

    float zs = 0.f;
    for (int e0 = 0; e0 < deg; e0 += 4) {
        int e = e0 + esub;
        if (e < deg) {
            int s = g_csr_src[off + e];
            float t = el[(size_t)s * NH + h] + er_h;
            t = (t > 0.f) ? t : 0.2f * t;
            zs += __expf(t - m);
        }
    }
    zs += __shfl_xor_sync(0xffffffffu, zs, 8);
    zs += __shfl_xor_sync(0xffffffffu, zs, 16);
    float zinv = 1.f / (zs + 1e-9f);

    int hc = lane >> 2;
    float m_c  = __shfl_sync(0xffffffffu, m, hc);
    float zi_c = __shfl_sync(0xffffffffu, zinv, hc);
    float er_c = __shfl_sync(0xffffffffu, er_h, hc);

    float4 acc = make_float4(0.f, 0.f, 0.f, 0.f);
    for (int e = 0; e < deg; e++) {
        int s = g_csr_src[off + e];
        float t = el[(size_t)s * NH + hc] + er_c;
        t = (t > 0.f) ? t : 0.2f * t;
        float w = __expf(t - m_c) * zi_c;
        float4 f = *(const float4*)(feat + (size_t)s * HD + lane * 4);
        acc.x = fmaf(f.x, w, acc.x);
        acc.y = fmaf(f.y, w, acc.y);
        acc.z = fmaf(f.z, w, acc.z);
        acc.w = fmaf(f.w, w, acc.w);
    }
    acc.x = fmaxf(acc.x, 0.f); acc.y = fmaxf(acc.y, 0.f);
    acc.z = fmaxf(acc.z, 0.f); acc.w = fmaxf(acc.w, 0.f);

    *(float4*)(zout + (size_t)n * HD + lane * 4) = acc;
    *(float4*)(out + (size_t)n * 384 + out_base + lane * 4) = acc;
}

// ---------------- launcher ----------------
extern "C" void kernel_launch(void* const* d_in, const int* in_sizes, int n_in,
                              void* d_out, int out_size)
{
    const float* obs = (const float*)d_in[0];
    const int*   src = (const int*)d_in[1];
    const int*   dst = (const int*)d_in[2];
    const float* W1  = (const float*)d_in[3];
    const float* b1  = (const float*)d_in[4];
    const float* W2  = (const float*)d_in[5];
    const float* b2  = (const float*)d_in[6];
    const float* Wg1 = (const float*)d_in[7];
    const float* al1 = (const float*)d_in[8];
    const float* ar1 = (const float*)d_in[9];
    const float* Wg2 = (const float*)d_in[10];
    const float* al2 = (const float*)d_in[11];
    const float* ar2 = (const float*)d_in[12];
    float* out = (float*)d_out;

    float *h1, *z1, *z2, *z3, *feat, *el, *er;
    __nv_bfloat16 *wth, *wtl;
    cudaGetSymbolAddress((void**)&h1,   g_h1);
    cudaGetSymbolAddress((void**)&z1,   g_z1);
    cudaGetSymbolAddress((void**)&z2,   g_z2);
    cudaGetSymbolAddress((void**)&z3,   g_z3);
    cudaGetSymbolAddress((void**)&feat, g_feat);
    cudaGetSymbolAddress((void**)&el,   g_el);
    cudaGetSymbolAddress((void**)&er,   g_er);
    cudaGetSymbolAddress((void**)&wth,  g_wt_hi);
    cudaGetSymbolAddress((void**)&wtl,  g_wt_lo);

    cudaFuncSetAttribute(gemm_mma, cudaFuncAttributeMaxDynamicSharedMemorySize, SM_TOTAL);

    // CSR build
    k_zero_deg<<<(NN + 255) / 256, 256>>>();
    k_hist<<<(NE + 255) / 256, 256>>>(dst);
    k_scan<<<1, 1024>>>();
    k_scatter<<<(NE + 255) / 256, 256>>>(src, dst);

    // weight transpose + split
    k_split<<<(512 * 256 + 255) / 256, 256>>>(W1,  OBSD, EHID, wth + W1T_OFF,  wtl + W1T_OFF);
    k_split<<<(128 * 512 + 255) / 256, 256>>>(W2,  EHID, HD,   wth + W2T_OFF,  wtl + W2T_OFF);
    k_split<<<(128 * 128 + 255) / 256, 256>>>(Wg1, HD,   HD,   wth + WG1T_OFF, wtl + WG1T_OFF);
    k_split<<<(128 * 128 + 255) / 256, 256>>>(Wg2, HD,   HD,   wth + WG2T_OFF, wtl + WG2T_OFF);

    int mblk = (NN + 127) / 128;
    // MLP
    gemm_mma<<<dim3(EHID / 128, mblk), 256, SM_TOTAL>>>(
        obs, wth + W1T_OFF, wtl + W1T_OFF, b1, h1, nullptr, 0, 0, NN, EHID, OBSD, 1);
    gemm_mma<<<dim3(1, mblk), 256, SM_TOTAL>>>(
        h1, wth + W2T_OFF, wtl + W2T_OFF, b2, z1, out, 384, 0, NN, HD, EHID, 1);

    // GAT layer 1
    gemm_mma<<<dim3(1, mblk), 256, SM_TOTAL>>>(
        z1, wth + WG1T_OFF, wtl + WG1T_OFF, nullptr, feat, nullptr, 0, 0, NN, HD, HD, 0);
    k_elr<<<(NN * NH + 255) / 256, 256>>>(feat, al1, ar1, el, er);
    gat_edge<<<(NN + 3) / 4, 128>>>(el, er, feat, z2, out, 128);

    // GAT layer 2
    gemm_mma<<<dim3(1, mblk), 256, SM_TOTAL>>>(
        z2, wth + WG2T_OFF, wtl + WG2T_OFF, nullptr, feat, nullptr, 0, 0, NN, HD, HD, 0);
    k_elr<<<(NN * NH + 255) / 256, 256>>>(feat, al2, ar2, el, er);
    gat_edge<<<(NN + 3) / 4, 128>>>(el, er, feat, z3, out, 256);
}

// round 4
// speedup vs baseline: 2.0458x; 1.0013x over previous
#include <cuda_runtime.h>
#include <cuda_bf16.h>
#include <math.h>
#include <stdint.h>

#define NN 50000
#define NE 600000
#define OBSD 256
#define EHID 512
#define HD 128
#define NH 8

// ---------------- scratch (device globals; no allocation allowed) ----------------
__device__ __align__(16) float g_h1[(size_t)NN * EHID];
__device__ __align__(16) float g_z1[(size_t)NN * HD];
__device__ __align__(16) float g_z2[(size_t)NN * HD];
__device__ __align__(16) float g_z3[(size_t)NN * HD];
__device__ __align__(16) float g_feat[(size_t)NN * HD];
__device__ __align__(16) float g_el[(size_t)NN * NH];
__device__ __align__(16) float g_er[(size_t)NN * NH];
__device__ int   g_deg[NN];
__device__ int   g_off[NN + 1];
__device__ int   g_pos[NN];
__device__ int   g_csr_src[NE];

// transposed + bf16-split weights: [N,K] K-major, hi and lo planes
#define W1T_OFF  0
#define W2T_OFF  (512*256)
#define WG1T_OFF (W2T_OFF + 128*512)
#define WG2T_OFF (WG1T_OFF + 128*128)
#define WT_TOTAL (WG2T_OFF + 128*128)
__device__ __align__(16) __nv_bfloat16 g_wt_hi[WT_TOTAL];
__device__ __align__(16) __nv_bfloat16 g_wt_lo[WT_TOTAL];

// ---------------- PTX helpers (baseline sm_80+ features only) ----------------
__device__ __forceinline__ uint32_t smem_u32(const void* p) {
    uint32_t a;
    asm("{ .reg .u64 t; cvta.to.shared.u64 t, %1; cvt.u32.u64 %0, t; }" : "=r"(a) : "l"(p));
    return a;
}

__device__ __forceinline__ void ldsm_x4(uint32_t& r0, uint32_t& r1, uint32_t& r2, uint32_t& r3,
                                        uint32_t addr) {
    asm volatile("ldmatrix.sync.aligned.m8n8.x4.shared.b16 {%0,%1,%2,%3}, [%4];"
                 : "=r"(r0), "=r"(r1), "=r"(r2), "=r"(r3) : "r"(addr));
}

__device__ __forceinline__ void mma_bf16(float* c,
                                         uint32_t a0, uint32_t a1, uint32_t a2, uint32_t a3,
                                         uint32_t b0, uint32_t b1) {
    asm volatile("mma.sync.aligned.m16n8k16.row.col.f32.bf16.bf16.f32 "
                 "{%0,%1,%2,%3}, {%4,%5,%6,%7}, {%8,%9}, {%0,%1,%2,%3};"
                 : "+f"(c[0]), "+f"(c[1]), "+f"(c[2]), "+f"(c[3])
                 : "r"(a0), "r"(a1), "r"(a2), "r"(a3), "r"(b0), "r"(b1));
}

__device__ __forceinline__ uint32_t sw128(uint32_t byte) {
    return byte ^ ((byte >> 3) & 0x70u);
}

__device__ __forceinline__ uint32_t pack_bf2(__nv_bfloat16 a, __nv_bfloat16 b) {
    __nv_bfloat162 t = __halves2bfloat162(a, b);
    return *reinterpret_cast<uint32_t*>(&t);
}

// ---------------- CSR build ----------------
__global__ void k_zero_deg() {
    int i = blockIdx.x * blockDim.x + threadIdx.x;
    if (i < NN) g_deg[i] = 0;
}

__global__ void k_hist(const int* __restrict__ dst) {
    int i = blockIdx.x * blockDim.x + threadIdx.x;
    if (i < NE) atomicAdd(&g_deg[dst[i]], 1);
}

__global__ void k_scan() {
    __shared__ int warpsums[32];
    __shared__ int s_run;
    int tid = threadIdx.x, lane = tid & 31, wid = tid >> 5;
    if (tid == 0) s_run = 0;
    __syncthreads();
    for (int base = 0; base < NN; base += 1024) {
        int i = base + tid;
        int v = (i < NN) ? g_deg[i] : 0;
        int x = v;
        #pragma unroll
        for (int s = 1; s < 32; s <<= 1) {
            int t = __shfl_up_sync(0xffffffffu, x, s);
            if (lane >= s) x += t;
        }
        if (lane == 31) warpsums[wid] = x;
        __syncthreads();
        if (wid == 0) {
            int w = warpsums[lane];
            #pragma unroll
            for (int s = 1; s < 32; s <<= 1) {
                int t = __shfl_up_sync(0xffffffffu, w, s);
                if (lane >= s) w += t;
            }
            warpsums[lane] = w;
        }
        __syncthreads();
        int chunk_total = warpsums[31];
        int prefix = s_run + ((wid > 0) ? warpsums[wid - 1] : 0) + x - v;
        if (i < NN) { g_off[i] = prefix; g_pos[i] = prefix; }
        __syncthreads();
        if (tid == 0) s_run += chunk_total;
        __syncthreads();
    }
    if (threadIdx.x == 0) g_off[NN] = s_run;
}

__global__ void k_scatter(const int* __restrict__ src, const int* __restrict__ dst) {
    int i = blockIdx.x * blockDim.x + threadIdx.x;
    if (i < NE) {
        int p = atomicAdd(&g_pos[dst[i]], 1);
        g_csr_src[p] = src[i];
    }
}

// ---------------- weight transpose + bf16 split: Wt[n,k] = W[k,n] ----------------
__global__ void k_split(const float* __restrict__ W, int K, int N,
                        __nv_bfloat16* __restrict__ hi, __nv_bfloat16* __restrict__ lo) {
    int idx = blockIdx.x * blockDim.x + threadIdx.x;
    if (idx >= N * K) return;
    int n = idx / K, k = idx - n * K;
    float x = W[(size_t)k * N + n];
    __nv_bfloat16 h = __float2bfloat16(x);
    hi[idx] = h;
    lo[idx] = __float2bfloat16(x - __bfloat162float(h));
}

// ---------------- bf16x3 mma.sync GEMM: C = relu?(A@B + bias) ----------------
// A: [M,K] fp32 row-major.  Bhi/Blo: [N,K] bf16 K-major.
// CTA tile 128x128, K-chunk 64. 256 threads = 8 warps, warp tile 64x32
// (warp_m = wid&1 -> 2x64 rows, warp_n = wid>>1 -> 4x32 cols).
// smem planes (128 rows x 128B, SW128 swizzle): Ahi, Alo, Bhi, Blo.
#define SMA_HI 0
#define SMA_LO 16384
#define SMB_HI 32768
#define SMB_LO 49152
#define SM_TOTAL 65536

__global__ __launch_bounds__(256) void gemm_mma(
    const float* __restrict__ A,
    const __nv_bfloat16* __restrict__ Bhi, const __nv_bfloat16* __restrict__ Blo,
    const float* __restrict__ bias,
    float* __restrict__ C, float* __restrict__ C2, int c2_stride, int c2_base,
    int M, int N, int K, int doRelu)
{
    extern __shared__ char sm[];
    uint32_t sb = smem_u32(sm);
    int tid = threadIdx.x, wid = tid >> 5, lane = tid & 31;
    int row0 = blockIdx.y * 128, col0 = blockIdx.x * 128;
    int wm = wid & 1, wn = wid >> 1;

    float acc[4][4][4];
    #pragma unroll
    for (int i = 0; i < 4; i++)
        #pragma unroll
        for (int j = 0; j < 4; j++)
            #pragma unroll
            for (int r = 0; r < 4; r++) acc[i][j][r] = 0.f;

    // ldmatrix lane address components
    // A frag (16x16): lanes 0-7 m0(rows0-7,k0-7), 8-15 m1(rows8-15,k0-7),
    //                 16-23 m2(rows0-7,k8-15), 24-31 m3(rows8-15,k8-15)
    int a_r  = lane & 15;                 // row within 16-row frag
    int a_kb = (lane >> 4) * 16;          // byte offset of k-half (8 bf16 = 16B)
    // B frag pair (16 n x 16 k): m0(n0-7,k0-7) m1(n0-7,k8-15) m2(n8-15,k0-7) m3(n8-15,k8-15)
    int b_n  = (lane & 7) + ((lane >> 4) & 1) * 8;
    int b_kb = ((lane >> 3) & 1) * 16;

    for (int c = 0; c < K / 64; c++) {
        int k0 = c * 64;
        // ---- load + split A tile: 128 rows x 64 cols fp32 -> hi/lo bf16 ----
        #pragma unroll
        for (int i = 0; i < 8; i++) {
            int idx = tid + i * 256;
            int r = idx >> 4, c4 = (idx & 15) << 2;
            float4 v = make_float4(0.f, 0.f, 0.f, 0.f);
            int gr = row0 + r;
            if (gr < M) v = *(const float4*)(A + (size_t)gr * K + k0 + c4);
            __nv_bfloat16 hx = __float2bfloat16(v.x), hy = __float2bfloat16(v.y);
            __nv_bfloat16 hz = __float2bfloat16(v.z), hw = __float2bfloat16(v.w);
            __nv_bfloat16 lx = __float2bfloat16(v.x - __bfloat162float(hx));
            __nv_bfloat16 ly = __float2bfloat16(v.y - __bfloat162float(hy));
            __nv_bfloat16 lz = __float2bfloat16(v.z - __bfloat162float(hz));
            __nv_bfloat16 lw = __float2bfloat16(v.w - __bfloat162float(hw));
            uint32_t sw = sw128((uint32_t)(r * 128 + c4 * 2));
            *(uint32_t*)(sm + SMA_HI + sw)     = pack_bf2(hx, hy);
            *(uint32_t*)(sm + SMA_HI + sw + 4) = pack_bf2(hz, hw);
            *(uint32_t*)(sm + SMA_LO + sw)     = pack_bf2(lx, ly);
            *(uint32_t*)(sm + SMA_LO + sw + 4) = pack_bf2(lz, lw);
        }
        // ---- load B tiles: 128 n-rows x 64 k bf16 (hi and lo) ----
        #pragma unroll
        for (int i = 0; i < 4; i++) {
            int idx = tid + i * 256;
            int r = idx >> 3, c8 = (idx & 7) << 3;
            size_t goff = (size_t)(col0 + r) * K + k0 + c8;
            uint4 vh = *(const uint4*)(Bhi + goff);
            uint4 vl = *(const uint4*)(Blo + goff);
            uint32_t sw = sw128((uint32_t)(r * 128 + c8 * 2));
            *(uint4*)(sm + SMB_HI + sw) = vh;
            *(uint4*)(sm + SMB_LO + sw) = vl;
        }
        __syncthreads();

        // ---- 3 precision planes: (Ahi,Bhi), (Ahi,Blo), (Alo,Bhi) ----
        #pragma unroll 1
        for (int pl = 0; pl < 3; pl++) {
            uint32_t abase = sb + (pl == 2 ? SMA_LO : SMA_HI);
            uint32_t bbase = sb + (pl == 1 ? SMB_LO : SMB_HI);
            #pragma unroll
            for (int k16 = 0; k16 < 4; k16++) {
                int kb = k16 * 32;  // 16 bf16 = 32 bytes
                uint32_t a[4][4], b[4][2];
                #pragma unroll
                for (int mf = 0; mf < 4; mf++) {
                    uint32_t byte = (uint32_t)((wm * 64 + mf * 16 + a_r) * 128 + kb + a_kb);
                    ldsm_x4(a[mf][0], a[mf][1], a[mf][2], a[mf][3], abase + sw128(byte));
                }
                #pragma unroll
                for (int nfp = 0; nfp < 2; nfp++) {
                    uint32_t byte = (uint32_t)((wn * 32 + nfp * 16 + b_n) * 128 + kb + b_kb);
                    uint32_t r0, r1, r2, r3;
                    ldsm_x4(r0, r1, r2, r3, bbase + sw128(byte));
                    b[nfp * 2][0] = r0; b[nfp * 2][1] = r1;
                    b[nfp * 2 + 1][0] = r2; b[nfp * 2 + 1][1] = r3;
                }
                #pragma unroll
                for (int mf = 0; mf < 4; mf++)
                    #pragma unroll
                    for (int nf = 0; nf < 4; nf++)
                        mma_bf16(acc[mf][nf], a[mf][0], a[mf][1], a[mf][2], a[mf][3],
                                 b[nf][0], b[nf][1]);
            }
        }
        __syncthreads();
    }

    // ---- epilogue ----
    // thread t holds: c0,c1 -> (row = t/4, col = (t%4)*2 + {0,1}); c2,c3 -> row+8
    int er_r = lane >> 2, er_c = (lane & 3) * 2;
    #pragma unroll
    for (int nf = 0; nf < 4; nf++) {
        int gc = col0 + wn * 32 + nf * 8 + er_c;
        float bx = 0.f, by = 0.f;
        if (bias) { bx = __ldg(bias + gc); by = __ldg(bias + gc + 1); }
        #pragma unroll
        for (int mf = 0; mf < 4; mf++) {
            int r_lo = row0 + wm * 64 + mf * 16 + er_r;
            float2 v0, v1;
            v0.x = acc[mf][nf][0] + bx; v0.y = acc[mf][nf][1] + by;
            v1.x = acc[mf][nf][2] + bx; v1.y = acc[mf][nf][3] + by;
            if (doRelu) {
                v0.x = fmaxf(v0.x, 0.f); v0.y = fmaxf(v0.y, 0.f);
                v1.x = fmaxf(v1.x, 0.f); v1.y = fmaxf(v1.y, 0.f);
            }
            if (r_lo < M) {
                *(float2*)(C + (size_t)r_lo * N + gc) = v0;
                if (C2) *(float2*)(C2 + (size_t)r_lo * c2_stride + c2_base + gc) = v0;
            }
            if (r_lo + 8 < M) {
                *(float2*)(C + (size_t)(r_lo + 8) * N + gc) = v1;
                if (C2) *(float2*)(C2 + (size_t)(r_lo + 8) * c2_stride + c2_base + gc) = v1;
            }
        }
    }
}

// ---------------- per-(node,head) attention logits el/er ----------------
__global__ void k_elr(const float* __restrict__ feat,
                      const float* __restrict__ al, const float* __restrict__ ar,
                      float* __restrict__ el, float* __restrict__ er)
{
    int idx = blockIdx.x * blockDim.x + threadIdx.x;
    if (idx >= NN * NH) return;
    int n = idx >> 3, h = idx & 7;
    const float* f = feat + (size_t)n * HD + h * 16;
    const float4* a4 = (const float4*)(al + h * 16);
    const float4* r4 = (const float4*)(ar + h * 16);
    float sl = 0.f, sr = 0.f;
    #pragma unroll
    for (int d = 0; d < 4; d++) {
        float4 fv = *(const float4*)(f + d * 4);
        float4 av = __ldg(a4 + d);
        float4 rv = __ldg(r4 + d);
        sl += fv.x * av.x + fv.y * av.y + fv.z * av.z + fv.w * av.w;
        sr += fv.x * rv.x + fv.y * rv.y + fv.z * rv.z + fv.w * rv.w;
    }
    el[idx] = sl;
    er[idx] = sr;
}

// ---------------- warp-per-node GAT softmax + aggregation ----------------
__global__ __launch_bounds__(128) void gat_edge(
    const float* __restrict__ el, const float* __restrict__ er,
    const float* __restrict__ feat,
    float* __restrict__ zout, float* __restrict__ out, int out_base)
{
    int n = blockIdx.x * 4 + (threadIdx.x >> 5);
    if (n >= NN) return;
    int lane = threadIdx.x & 31;
    int off = g_off[n];
    int deg = g_off[n + 1] - off;

    const float NEG_INF = -__int_as_float(0x7f800000);

    int h = lane & 7, esub = lane >> 3;
    float er_h = er[(size_t)n * NH + h];

    float m = NEG_INF;
    for (int e0 = 0; e0 < deg; e0 += 4) {
        int e = e0 + esub;
        float x = NEG_INF;
        if (e < deg) {
            int s = g_csr_src[off + e];
            float t = el[(size_t)s * NH + h] + er_h;
            x = (t > 0.f) ? t : 0.2f * t;
        }
        m = fmaxf(m, x);
    }
    m = fmaxf(m, __shfl_xor_sync(0xffffffffu, m, 8));
    m = fmaxf(m, __shfl_xor_sync(0xffffffffu, m, 16));
    if (!isfinite(m)) m = 0.f;

    float zs = 0.f;
    for (int e0 = 0; e0 < deg; e0 += 4) {
        int e = e0 + esub;
        if (e < deg) {
            int s = g_csr_src[off + e];
            float t = el[(size_t)s * NH + h] + er_h;
            t = (t > 0.f) ? t : 0.2f * t;
            zs += __expf(t - m);
        }
    }
    zs += __shfl_xor_sync(0xffffffffu, zs, 8);
    zs += __shfl_xor_sync(0xffffffffu, zs, 16);
    float zinv = 1.f / (zs + 1e-9f);

    int hc = lane >> 2;
    float m_c  = __shfl_sync(0xffffffffu, m, hc);
    float zi_c = __shfl_sync(0xffffffffu, zinv, hc);
    float er_c = __shfl_sync(0xffffffffu, er_h, hc);

    float4 acc = make_float4(0.f, 0.f, 0.f, 0.f);
    for (int e = 0; e < deg; e++) {
        int s = g_csr_src[off + e];
        float t = el[(size_t)s * NH + hc] + er_c;
        t = (t > 0.f) ? t : 0.2f * t;
        float w = __expf(t - m_c) * zi_c;
        float4 f = *(const float4*)(feat + (size_t)s * HD + lane * 4);
        acc.x = fmaf(f.x, w, acc.x);
        acc.y = fmaf(f.y, w, acc.y);
        acc.z = fmaf(f.z, w, acc.z);
        acc.w = fmaf(f.w, w, acc.w);
    }
    acc.x = fmaxf(acc.x, 0.f); acc.y = fmaxf(acc.y, 0.f);
    acc.z = fmaxf(acc.z, 0.f); acc.w = fmaxf(acc.w, 0.f);

    *(float4*)(zout + (size_t)n * HD + lane * 4) = acc;
    *(float4*)(out + (size_t)n * 384 + out_base + lane * 4) = acc;
}

// ---------------- launcher ----------------
extern "C" void kernel_launch(void* const* d_in, const int* in_sizes, int n_in,
                              void* d_out, int out_size)
{
    const float* obs = (const float*)d_in[0];
    const int*   src = (const int*)d_in[1];
    const int*   dst = (const int*)d_in[2];
    const float* W1  = (const float*)d_in[3];
    const float* b1  = (const float*)d_in[4];
    const float* W2  = (const float*)d_in[5];
    const float* b2  = (const float*)d_in[6];
    const float* Wg1 = (const float*)d_in[7];
    const float* al1 = (const float*)d_in[8];
    const float* ar1 = (const float*)d_in[9];
    const float* Wg2 = (const float*)d_in[10];
    const float* al2 = (const float*)d_in[11];
    const float* ar2 = (const float*)d_in[12];
    float* out = (float*)d_out;

    float *h1, *z1, *z2, *z3, *feat, *el, *er;
    __nv_bfloat16 *wth, *wtl;
    cudaGetSymbolAddress((void**)&h1,   g_h1);
    cudaGetSymbolAddress((void**)&z1,   g_z1);
    cudaGetSymbolAddress((void**)&z2,   g_z2);
    cudaGetSymbolAddress((void**)&z3,   g_z3);
    cudaGetSymbolAddress((void**)&feat, g_feat);
    cudaGetSymbolAddress((void**)&el,   g_el);
    cudaGetSymbolAddress((void**)&er,   g_er);
    cudaGetSymbolAddress((void**)&wth,  g_wt_hi);
    cudaGetSymbolAddress((void**)&wtl,  g_wt_lo);

    cudaFuncSetAttribute(gemm_mma, cudaFuncAttributeMaxDynamicSharedMemorySize, SM_TOTAL);

    // CSR build
    k_zero_deg<<<(NN + 255) / 256, 256>>>();
    k_hist<<<(NE + 255) / 256, 256>>>(dst);
    k_scan<<<1, 1024>>>();
    k_scatter<<<(NE + 255) / 256, 256>>>(src, dst);

    // weight transpose + split
    k_split<<<(512 * 256 + 255) / 256, 256>>>(W1,  OBSD, EHID, wth + W1T_OFF,  wtl + W1T_OFF);
    k_split<<<(128 * 512 + 255) / 256, 256>>>(W2,  EHID, HD,   wth + W2T_OFF,  wtl + W2T_OFF);
    k_split<<<(128 * 128 + 255) / 256, 256>>>(Wg1, HD,   HD,   wth + WG1T_OFF, wtl + WG1T_OFF);
    k_split<<<(128 * 128 + 255) / 256, 256>>>(Wg2, HD,   HD,   wth + WG2T_OFF, wtl + WG2T_OFF);

    int mblk = (NN + 127) / 128;
    // MLP
    gemm_mma<<<dim3(EHID / 128, mblk), 256, SM_TOTAL>>>(
        obs, wth + W1T_OFF, wtl + W1T_OFF, b1, h1, nullptr, 0, 0, NN, EHID, OBSD, 1);
    gemm_mma<<<dim3(1, mblk), 256, SM_TOTAL>>>(
        h1, wth + W2T_OFF, wtl + W2T_OFF, b2, z1, out, 384, 0, NN, HD, EHID, 1);

    // GAT layer 1
    gemm_mma<<<dim3(1, mblk), 256, SM_TOTAL>>>(
        z1, wth + WG1T_OFF, wtl + WG1T_OFF, nullptr, feat, nullptr, 0, 0, NN, HD, HD, 0);
    k_elr<<<(NN * NH + 255) / 256, 256>>>(feat, al1, ar1, el, er);
    gat_edge<<<(NN + 3) / 4, 128>>>(el, er, feat, z2, out, 128);

    // GAT layer 2
    gemm_mma<<<dim3(1, mblk), 256, SM_TOTAL>>>(
        z2, wth + WG2T_OFF, wtl + WG2T_OFF, nullptr, feat, nullptr, 0, 0, NN, HD, HD, 0);
    k_elr<<<(NN * NH + 255) / 256, 256>>>(feat, al2, ar2, el, er);
    gat_edge<<<(NN + 3) / 4, 128>>>(el, er, feat, z3, out, 256);
}

// round 5
// speedup vs baseline: 2.0485x; 1.0013x over previous
#include <cuda_runtime.h>
#include <cuda_bf16.h>
#include <math.h>
#include <stdint.h>

#define NN 50000
#define NE 600000
#define OBSD 256
#define EHID 512
#define HD 128
#define NH 8

// ---------------- scratch (device globals; no allocation allowed) ----------------
__device__ __align__(16) float g_h1[(size_t)NN * EHID];
__device__ __align__(16) float g_z1[(size_t)NN * HD];
__device__ __align__(16) float g_z2[(size_t)NN * HD];
__device__ __align__(16) float g_z3[(size_t)NN * HD];
__device__ __align__(16) float g_feat[(size_t)NN * HD];
__device__ __align__(16) float g_el[(size_t)NN * NH];
__device__ __align__(16) float g_er[(size_t)NN * NH];
__device__ int   g_deg[NN];
__device__ int   g_off[NN + 1];
__device__ int   g_pos[NN];
__device__ int   g_csr_src[NE];

// transposed + bf16-split weights: [N,K] K-major, hi and lo planes
#define W1T_OFF  0
#define W2T_OFF  (512*256)
#define WG1T_OFF (W2T_OFF + 128*512)
#define WG2T_OFF (WG1T_OFF + 128*128)
#define WT_TOTAL (WG2T_OFF + 128*128)
__device__ __align__(16) __nv_bfloat16 g_wt_hi[WT_TOTAL];
__device__ __align__(16) __nv_bfloat16 g_wt_lo[WT_TOTAL];

// ---------------- PTX helpers (baseline sm_80+ features only) ----------------
__device__ __forceinline__ uint32_t smem_u32(const void* p) {
    uint32_t a;
    asm("{ .reg .u64 t; cvta.to.shared.u64 t, %1; cvt.u32.u64 %0, t; }" : "=r"(a) : "l"(p));
    return a;
}

__device__ __forceinline__ void ldsm_x4(uint32_t& r0, uint32_t& r1, uint32_t& r2, uint32_t& r3,
                                        uint32_t addr) {
    asm volatile("ldmatrix.sync.aligned.m8n8.x4.shared.b16 {%0,%1,%2,%3}, [%4];"
                 : "=r"(r0), "=r"(r1), "=r"(r2), "=r"(r3) : "r"(addr));
}

__device__ __forceinline__ void mma_bf16(float* c,
                                         uint32_t a0, uint32_t a1, uint32_t a2, uint32_t a3,
                                         uint32_t b0, uint32_t b1) {
    asm volatile("mma.sync.aligned.m16n8k16.row.col.f32.bf16.bf16.f32 "
                 "{%0,%1,%2,%3}, {%4,%5,%6,%7}, {%8,%9}, {%0,%1,%2,%3};"
                 : "+f"(c[0]), "+f"(c[1]), "+f"(c[2]), "+f"(c[3])
                 : "r"(a0), "r"(a1), "r"(a2), "r"(a3), "r"(b0), "r"(b1));
}

__device__ __forceinline__ uint32_t sw128(uint32_t byte) {
    return byte ^ ((byte >> 3) & 0x70u);
}

__device__ __forceinline__ uint32_t pack_bf2(__nv_bfloat16 a, __nv_bfloat16 b) {
    __nv_bfloat162 t = __halves2bfloat162(a, b);
    return *reinterpret_cast<uint32_t*>(&t);
}

// ---------------- CSR build ----------------
__global__ void k_zero_deg() {
    int i = blockIdx.x * blockDim.x + threadIdx.x;
    if (i < NN) g_deg[i] = 0;
}

__global__ void k_hist(const int* __restrict__ dst) {
    int i = blockIdx.x * blockDim.x + threadIdx.x;
    if (i < NE) atomicAdd(&g_deg[dst[i]], 1);
}

__global__ void k_scan() {
    __shared__ int warpsums[32];
    __shared__ int s_run;
    int tid = threadIdx.x, lane = tid & 31, wid = tid >> 5;
    if (tid == 0) s_run = 0;
    __syncthreads();
    for (int base = 0; base < NN; base += 1024) {
        int i = base + tid;
        int v = (i < NN) ? g_deg[i] : 0;
        int x = v;
        #pragma unroll
        for (int s = 1; s < 32; s <<= 1) {
            int t = __shfl_up_sync(0xffffffffu, x, s);
            if (lane >= s) x += t;
        }
        if (lane == 31) warpsums[wid] = x;
        __syncthreads();
        if (wid == 0) {
            int w = warpsums[lane];
            #pragma unroll
            for (int s = 1; s < 32; s <<= 1) {
                int t = __shfl_up_sync(0xffffffffu, w, s);
                if (lane >= s) w += t;
            }
            warpsums[lane] = w;
        }
        __syncthreads();
        int chunk_total = warpsums[31];
        int prefix = s_run + ((wid > 0) ? warpsums[wid - 1] : 0) + x - v;
        if (i < NN) { g_off[i] = prefix; g_pos[i] = prefix; }
        __syncthreads();
        if (tid == 0) s_run += chunk_total;
        __syncthreads();
    }
    if (threadIdx.x == 0) g_off[NN] = s_run;
}

__global__ void k_scatter(const int* __restrict__ src, const int* __restrict__ dst) {
    int i = blockIdx.x * blockDim.x + threadIdx.x;
    if (i < NE) {
        int p = atomicAdd(&g_pos[dst[i]], 1);
        g_csr_src[p] = src[i];
    }
}

// ---------------- weight transpose + bf16 split: Wt[n,k] = W[k,n] ----------------
__global__ void k_split(const float* __restrict__ W, int K, int N,
                        __nv_bfloat16* __restrict__ hi, __nv_bfloat16* __restrict__ lo) {
    int idx = blockIdx.x * blockDim.x + threadIdx.x;
    if (idx >= N * K) return;
    int n = idx / K, k = idx - n * K;
    float x = W[(size_t)k * N + n];
    __nv_bfloat16 h = __float2bfloat16(x);
    hi[idx] = h;
    lo[idx] = __float2bfloat16(x - __bfloat162float(h));
}

// ---------------- bf16x3 mma.sync GEMM: C = relu?(A@B + bias) ----------------
// A: [M,K] fp32 row-major.  Bhi/Blo: [N,K] bf16 K-major.
// CTA tile 128x128, K-chunk 64. 256 threads = 8 warps, warp tile 64x32
// (warp_m = wid&1 -> 2x64 rows, warp_n = wid>>1 -> 4x32 cols).
// smem planes (128 rows x 128B, SW128 swizzle): Ahi, Alo, Bhi, Blo.
#define SMA_HI 0
#define SMA_LO 16384
#define SMB_HI 32768
#define SMB_LO 49152
#define SM_TOTAL 65536

__global__ __launch_bounds__(256) void gemm_mma(
    const float* __restrict__ A,
    const __nv_bfloat16* __restrict__ Bhi, const __nv_bfloat16* __restrict__ Blo,
    const float* __restrict__ bias,
    float* __restrict__ C, float* __restrict__ C2, int c2_stride, int c2_base,
    int M, int N, int K, int doRelu)
{
    extern __shared__ char sm[];
    uint32_t sb = smem_u32(sm);
    int tid = threadIdx.x, wid = tid >> 5, lane = tid & 31;
    int row0 = blockIdx.y * 128, col0 = blockIdx.x * 128;
    int wm = wid & 1, wn = wid >> 1;

    float acc[4][4][4];
    #pragma unroll
    for (int i = 0; i < 4; i++)
        #pragma unroll
        for (int j = 0; j < 4; j++)
            #pragma unroll
            for (int r = 0; r < 4; r++) acc[i][j][r] = 0.f;

    // ldmatrix lane address components
    // A frag (16x16): lanes 0-7 m0(rows0-7,k0-7), 8-15 m1(rows8-15,k0-7),
    //                 16-23 m2(rows0-7,k8-15), 24-31 m3(rows8-15,k8-15)
    int a_r  = lane & 15;                 // row within 16-row frag
    int a_kb = (lane >> 4) * 16;          // byte offset of k-half (8 bf16 = 16B)
    // B frag pair (16 n x 16 k): m0(n0-7,k0-7) m1(n0-7,k8-15) m2(n8-15,k0-7) m3(n8-15,k8-15)
    int b_n  = (lane & 7) + ((lane >> 4) & 1) * 8;
    int b_kb = ((lane >> 3) & 1) * 16;

    for (int c = 0; c < K / 64; c++) {
        int k0 = c * 64;
        // ---- load + split A tile: 128 rows x 64 cols fp32 -> hi/lo bf16 ----
        #pragma unroll
        for (int i = 0; i < 8; i++) {
            int idx = tid + i * 256;
            int r = idx >> 4, c4 = (idx & 15) << 2;
            float4 v = make_float4(0.f, 0.f, 0.f, 0.f);
            int gr = row0 + r;
            if (gr < M) v = *(const float4*)(A + (size_t)gr * K + k0 + c4);
            __nv_bfloat16 hx = __float2bfloat16(v.x), hy = __float2bfloat16(v.y);
            __nv_bfloat16 hz = __float2bfloat16(v.z), hw = __float2bfloat16(v.w);
            __nv_bfloat16 lx = __float2bfloat16(v.x - __bfloat162float(hx));
            __nv_bfloat16 ly = __float2bfloat16(v.y - __bfloat162float(hy));
            __nv_bfloat16 lz = __float2bfloat16(v.z - __bfloat162float(hz));
            __nv_bfloat16 lw = __float2bfloat16(v.w - __bfloat162float(hw));
            uint32_t sw = sw128((uint32_t)(r * 128 + c4 * 2));
            *(uint32_t*)(sm + SMA_HI + sw)     = pack_bf2(hx, hy);
            *(uint32_t*)(sm + SMA_HI + sw + 4) = pack_bf2(hz, hw);
            *(uint32_t*)(sm + SMA_LO + sw)     = pack_bf2(lx, ly);
            *(uint32_t*)(sm + SMA_LO + sw + 4) = pack_bf2(lz, lw);
        }
        // ---- load B tiles: 128 n-rows x 64 k bf16 (hi and lo) ----
        #pragma unroll
        for (int i = 0; i < 4; i++) {
            int idx = tid + i * 256;
            int r = idx >> 3, c8 = (idx & 7) << 3;
            size_t goff = (size_t)(col0 + r) * K + k0 + c8;
            uint4 vh = *(const uint4*)(Bhi + goff);
            uint4 vl = *(const uint4*)(Blo + goff);
            uint32_t sw = sw128((uint32_t)(r * 128 + c8 * 2));
            *(uint4*)(sm + SMB_HI + sw) = vh;
            *(uint4*)(sm + SMB_LO + sw) = vl;
        }
        __syncthreads();

        // ---- 3 precision planes: (Ahi,Bhi), (Ahi,Blo), (Alo,Bhi) ----
        #pragma unroll 1
        for (int pl = 0; pl < 3; pl++) {
            uint32_t abase = sb + (pl == 2 ? SMA_LO : SMA_HI);
            uint32_t bbase = sb + (pl == 1 ? SMB_LO : SMB_HI);
            #pragma unroll
            for (int k16 = 0; k16 < 4; k16++) {
                int kb = k16 * 32;  // 16 bf16 = 32 bytes
                uint32_t a[4][4], b[4][2];
                #pragma unroll
                for (int mf = 0; mf < 4; mf++) {
                    uint32_t byte = (uint32_t)((wm * 64 + mf * 16 + a_r) * 128 + kb + a_kb);
                    ldsm_x4(a[mf][0], a[mf][1], a[mf][2], a[mf][3], abase + sw128(byte));
                }
                #pragma unroll
                for (int nfp = 0; nfp < 2; nfp++) {
                    uint32_t byte = (uint32_t)((wn * 32 + nfp * 16 + b_n) * 128 + kb + b_kb);
                    uint32_t r0, r1, r2, r3;
                    ldsm_x4(r0, r1, r2, r3, bbase + sw128(byte));
                    b[nfp * 2][0] = r0; b[nfp * 2][1] = r1;
                    b[nfp * 2 + 1][0] = r2; b[nfp * 2 + 1][1] = r3;
                }
                #pragma unroll
                for (int mf = 0; mf < 4; mf++)
                    #pragma unroll
                    for (int nf = 0; nf < 4; nf++)
                        mma_bf16(acc[mf][nf], a[mf][0], a[mf][1], a[mf][2], a[mf][3],
                                 b[nf][0], b[nf][1]);
            }
        }
        __syncthreads();
    }

    // ---- epilogue ----
    // thread t holds: c0,c1 -> (row = t/4, col = (t%4)*2 + {0,1}); c2,c3 -> row+8
    int er_r = lane >> 2, er_c = (lane & 3) * 2;
    #pragma unroll
    for (int nf = 0; nf < 4; nf++) {
        int gc = col0 + wn * 32 + nf * 8 + er_c;
        float bx = 0.f, by = 0.f;
        if (bias) { bx = __ldg(bias + gc); by = __ldg(bias + gc + 1); }
        #pragma unroll
        for (int mf = 0; mf < 4; mf++) {
            int r_lo = row0 + wm * 64 + mf * 16 + er_r;
            float2 v0, v1;
            v0.x = acc[mf][nf][0] + bx; v0.y = acc[mf][nf][1] + by;
            v1.x = acc[mf][nf][2] + bx; v1.y = acc[mf][nf][3] + by;
            if (doRelu) {
                v0.x = fmaxf(v0.x, 0.f); v0.y = fmaxf(v0.y, 0.f);
                v1.x = fmaxf(v1.x, 0.f); v1.y = fmaxf(v1.y, 0.f);
            }
            if (r_lo < M) {
                *(float2*)(C + (size_t)r_lo * N + gc) = v0;
                if (C2) *(float2*)(C2 + (size_t)r_lo * c2_stride + c2_base + gc) = v0;
            }
            if (r_lo + 8 < M) {
                *(float2*)(C + (size_t)(r_lo + 8) * N + gc) = v1;
                if (C2) *(float2*)(C2 + (size_t)(r_lo + 8) * c2_stride + c2_base + gc) = v1;
            }
        }
    }
}

// ---------------- per-(node,head) attention logits el/er ----------------
__global__ void k_elr(const float* __restrict__ feat,
                      const float* __restrict__ al, const float* __restrict__ ar,
                      float* __restrict__ el, float* __restrict__ er)
{
    int idx = blockIdx.x * blockDim.x + threadIdx.x;
    if (idx >= NN * NH) return;
    int n = idx >> 3, h = idx & 7;
    const float* f = feat + (size_t)n * HD + h * 16;
    const float4* a4 = (const float4*)(al + h * 16);
    const float4* r4 = (const float4*)(ar + h * 16);
    float sl = 0.f, sr = 0.f;
    #pragma unroll
    for (int d = 0; d < 4; d++) {
        float4 fv = *(const float4*)(f + d * 4);
        float4 av = __ldg(a4 + d);
        float4 rv = __ldg(r4 + d);
        sl += fv.x * av.x + fv.y * av.y + fv.z * av.z + fv.w * av.w;
        sr += fv.x * rv.x + fv.y * rv.y + fv.z * rv.z + fv.w * rv.w;
    }
    el[idx] = sl;
    er[idx] = sr;
}

// ---------------- warp-per-node GAT softmax + aggregation ----------------
__global__ __launch_bounds__(128) void gat_edge(
    const float* __restrict__ el, const float* __restrict__ er,
    const float* __restrict__ feat,
    float* __restrict__ zout, float* __restrict__ out, int out_base)
{
    int n = blockIdx.x * 4 + (threadIdx.x >> 5);
    if (n >= NN) return;
    int lane = threadIdx.x & 31;
    int off = g_off[n];
    int deg = g_off[n + 1] - off;

    const float NEG_INF = -__int_as_float(0x7f800000);

    int h = lane & 7, esub = lane >> 3;
    float er_h = er[(size_t)n * NH + h];

    float m = NEG_INF;
    for (int e0 = 0; e0 < deg; e0 += 4) {
        int e = e0 + esub;
        float x = NEG_INF;
        if (e < deg) {
            int s = g_csr_src[off + e];
            float t = el[(size_t)s * NH + h] + er_h;
            x = (t > 0.f) ? t : 0.2f * t;
        }
        m = fmaxf(m, x);
    }
    m = fmaxf(m, __shfl_xor_sync(0xffffffffu, m, 8));
    m = fmaxf(m, __shfl_xor_sync(0xffffffffu, m, 16));
    if (!isfinite(m)) m = 0.f;

    float zs = 0.f;
    for (int e0 = 0; e0 < deg; e0 += 4) {
        int e = e0 + esub;
        if (e < deg) {
            int s = g_csr_src[off + e];
            float t = el[(size_t)s * NH + h] + er_h;
            t = (t > 0.f) ? t : 0.2f * t;
            zs += __expf(t - m);
        }
    }
    zs += __shfl_xor_sync(0xffffffffu, zs, 8);
    zs += __shfl_xor_sync(0xffffffffu, zs, 16);
    float zinv = 1.f / (zs + 1e-9f);

    int hc = lane >> 2;
    float m_c  = __shfl_sync(0xffffffffu, m, hc);
    float zi_c = __shfl_sync(0xffffffffu, zinv, hc);
    float er_c = __shfl_sync(0xffffffffu, er_h, hc);

    float4 acc = make_float4(0.f, 0.f, 0.f, 0.f);
    for (int e = 0; e < deg; e++) {
        int s = g_csr_src[off + e];
        float t = el[(size_t)s * NH + hc] + er_c;
        t = (t > 0.f) ? t : 0.2f * t;
        float w = __expf(t - m_c) * zi_c;
        float4 f = *(const float4*)(feat + (size_t)s * HD + lane * 4);
        acc.x = fmaf(f.x, w, acc.x);
        acc.y = fmaf(f.y, w, acc.y);
        acc.z = fmaf(f.z, w, acc.z);
        acc.w = fmaf(f.w, w, acc.w);
    }
    acc.x = fmaxf(acc.x, 0.f); acc.y = fmaxf(acc.y, 0.f);
    acc.z = fmaxf(acc.z, 0.f); acc.w = fmaxf(acc.w, 0.f);

    *(float4*)(zout + (size_t)n * HD + lane * 4) = acc;
    *(float4*)(out + (size_t)n * 384 + out_base + lane * 4) = acc;
}

// ---------------- launcher ----------------
extern "C" void kernel_launch(void* const* d_in, const int* in_sizes, int n_in,
                              void* d_out, int out_size)
{
    const float* obs = (const float*)d_in[0];
    const int*   src = (const int*)d_in[1];
    const int*   dst = (const int*)d_in[2];
    const float* W1  = (const float*)d_in[3];
    const float* b1  = (const float*)d_in[4];
    const float* W2  = (const float*)d_in[5];
    const float* b2  = (const float*)d_in[6];
    const float* Wg1 = (const float*)d_in[7];
    const float* al1 = (const float*)d_in[8];
    const float* ar1 = (const float*)d_in[9];
    const float* Wg2 = (const float*)d_in[10];
    const float* al2 = (const float*)d_in[11];
    const float* ar2 = (const float*)d_in[12];
    float* out = (float*)d_out;

    float *h1, *z1, *z2, *z3, *feat, *el, *er;
    __nv_bfloat16 *wth, *wtl;
    cudaGetSymbolAddress((void**)&h1,   g_h1);
    cudaGetSymbolAddress((void**)&z1,   g_z1);
    cudaGetSymbolAddress((void**)&z2,   g_z2);
    cudaGetSymbolAddress((void**)&z3,   g_z3);
    cudaGetSymbolAddress((void**)&feat, g_feat);
    cudaGetSymbolAddress((void**)&el,   g_el);
    cudaGetSymbolAddress((void**)&er,   g_er);
    cudaGetSymbolAddress((void**)&wth,  g_wt_hi);
    cudaGetSymbolAddress((void**)&wtl,  g_wt_lo);

    cudaFuncSetAttribute(gemm_mma, cudaFuncAttributeMaxDynamicSharedMemorySize, SM_TOTAL);

    // CSR build
    k_zero_deg<<<(NN + 255) / 256, 256>>>();
    k_hist<<<(NE + 255) / 256, 256>>>(dst);
    k_scan<<<1, 1024>>>();
    k_scatter<<<(NE + 255) / 256, 256>>>(src, dst);

    // weight transpose + split
    k_split<<<(512 * 256 + 255) / 256, 256>>>(W1,  OBSD, EHID, wth + W1T_OFF,  wtl + W1T_OFF);
    k_split<<<(128 * 512 + 255) / 256, 256>>>(W2,  EHID, HD,   wth + W2T_OFF,  wtl + W2T_OFF);
    k_split<<<(128 * 128 + 255) / 256, 256>>>(Wg1, HD,   HD,   wth + WG1T_OFF, wtl + WG1T_OFF);
    k_split<<<(128 * 128 + 255) / 256, 256>>>(Wg2, HD,   HD,   wth + WG2T_OFF, wtl + WG2T_OFF);

    int mblk = (NN + 127) / 128;
    // MLP
    gemm_mma<<<dim3(EHID / 128, mblk), 256, SM_TOTAL>>>(
        obs, wth + W1T_OFF, wtl + W1T_OFF, b1, h1, nullptr, 0, 0, NN, EHID, OBSD, 1);
    gemm_mma<<<dim3(1, mblk), 256, SM_TOTAL>>>(
        h1, wth + W2T_OFF, wtl + W2T_OFF, b2, z1, out, 384, 0, NN, HD, EHID, 1);

    // GAT layer 1
    gemm_mma<<<dim3(1, mblk), 256, SM_TOTAL>>>(
        z1, wth + WG1T_OFF, wtl + WG1T_OFF, nullptr, feat, nullptr, 0, 0, NN, HD, HD, 0);
    k_elr<<<(NN * NH + 255) / 256, 256>>>(feat, al1, ar1, el, er);
    gat_edge<<<(NN + 3) / 4, 128>>>(el, er, feat, z2, out, 128);

    // GAT layer 2
    gemm_mma<<<dim3(1, mblk), 256, SM_TOTAL>>>(
        z2, wth + WG2T_OFF, wtl + WG2T_OFF, nullptr, feat, nullptr, 0, 0, NN, HD, HD, 0);
    k_elr<<<(NN * NH + 255) / 256, 256>>>(feat, al2, ar2, el, er);
    gat_edge<<<(NN + 3) / 4, 128>>>(el, er, feat, z3, out, 256);
}